// round 1
// baseline (speedup 1.0000x reference)
#include <cuda_runtime.h>
#include <math_constants.h>

#define TW 128
#define TH 16
#define EPSV 1e-5f

// x: [8, 1, 3, 1536, 1536] f32.  mp over (depth=3 full, 3x3 spatial pad 1).
// out = (x - mp + EPS > 0) ? x : 0, mp broadcast over depth.
__global__ __launch_bounds__(256) void nms3d_kernel(const float* __restrict__ x,
                                                    float* __restrict__ out) {
    const int W = 1536, H = 1536;
    const long long plane = (long long)W * H;  // 2359296

    const int b  = blockIdx.z;
    const int h0 = blockIdx.y * TH;
    const int w0 = blockIdx.x * TW;

    const float* xb = x   + (long long)b * 3 * plane;
    float*       ob = out + (long long)b * 3 * plane;

    __shared__ float z[(TH + 2) * (TW + 2)];   // depth-max with halo
    __shared__ float rm[(TH + 2) * TW];        // horizontal 3-tap max

    const int tid = threadIdx.x;

    // ---- Phase 1: depth max into shared (with -inf halo at image borders) ----
    for (int i = tid; i < (TH + 2) * (TW + 2); i += 256) {
        int r = i / (TW + 2);
        int c = i % (TW + 2);
        int h = h0 + r - 1;
        int w = w0 + c - 1;
        float v = -CUDART_INF_F;
        if (h >= 0 && h < H && w >= 0 && w < W) {
            long long off = (long long)h * W + w;
            float a0 = xb[off];
            float a1 = xb[off + plane];
            float a2 = xb[off + 2 * plane];
            v = fmaxf(fmaxf(a0, a1), a2);
        }
        z[i] = v;
    }
    __syncthreads();

    // ---- Phase 2: horizontal 3-tap max ----
    for (int i = tid; i < (TH + 2) * TW; i += 256) {
        int r = i / TW;
        int c = i % TW;
        const float* zr = &z[r * (TW + 2) + c];
        rm[i] = fmaxf(fmaxf(zr[0], zr[1]), zr[2]);
    }
    __syncthreads();

    // ---- Phase 3: vertical 3-tap max, mask, vectorized write ----
    // 512 float4-pixels per tile, 2 iterations of 256 threads.
    for (int i = tid; i < TH * (TW / 4); i += 256) {
        int r  = i / (TW / 4);
        int c4 = (i % (TW / 4)) * 4;

        float mp[4];
#pragma unroll
        for (int j = 0; j < 4; j++) {
            int c = c4 + j;
            mp[j] = fmaxf(fmaxf(rm[r * TW + c], rm[(r + 1) * TW + c]),
                          rm[(r + 2) * TW + c]);
        }

        long long off = (long long)(h0 + r) * W + (w0 + c4);
#pragma unroll
        for (int d = 0; d < 3; d++) {
            float4 v = *(const float4*)(xb + off + d * plane);
            float4 o;
            o.x = (v.x - mp[0] + EPSV > 0.f) ? v.x : 0.f;
            o.y = (v.y - mp[1] + EPSV > 0.f) ? v.y : 0.f;
            o.z = (v.z - mp[2] + EPSV > 0.f) ? v.z : 0.f;
            o.w = (v.w - mp[3] + EPSV > 0.f) ? v.w : 0.f;
            *(float4*)(ob + off + d * plane) = o;
        }
    }
}

extern "C" void kernel_launch(void* const* d_in, const int* in_sizes, int n_in,
                              void* d_out, int out_size) {
    const float* x = (const float*)d_in[0];
    float* out = (float*)d_out;
    dim3 grid(1536 / TW, 1536 / TH, 8);   // (12, 96, 8)
    nms3d_kernel<<<grid, 256>>>(x, out);
}

// round 2
// speedup vs baseline: 1.2564x; 1.2564x over previous
#include <cuda_runtime.h>

#define RS 16        // rows per warp strip
#define EPSV 1e-5f
#define NEG_INF __int_as_float(0xff800000)

static __device__ __forceinline__ float fmax3(float a, float b, float c) {
    return fmaxf(fmaxf(a, b), c);
}

// Process one image row y for this warp's 128-wide strip:
// loads 3 depth planes (float4/lane), computes depth-max then horizontal
// 3-tap max (with warp-edge halo), returns hm; x values returned in xa[3].
static __device__ __forceinline__ float4 row_hmax(
    const float* __restrict__ xb, long long plane, int W, int H,
    int y, int col, int hcol, bool hvalid, int lane, float4 xa[3])
{
    float4 dm;
    float hl = NEG_INF;
    if (y >= 0 && y < H) {
        const float* p = xb + (long long)y * W + col;
        xa[0] = *(const float4*)(p);
        xa[1] = *(const float4*)(p + plane);
        xa[2] = *(const float4*)(p + 2 * plane);
        if (hvalid) {
            const float* q = xb + (long long)y * W + hcol;
            hl = fmax3(q[0], q[plane], q[2 * plane]);
        }
        dm.x = fmax3(xa[0].x, xa[1].x, xa[2].x);
        dm.y = fmax3(xa[0].y, xa[1].y, xa[2].y);
        dm.z = fmax3(xa[0].z, xa[1].z, xa[2].z);
        dm.w = fmax3(xa[0].w, xa[1].w, xa[2].w);
    } else {
        dm.x = dm.y = dm.z = dm.w = NEG_INF;
    }
    float dl = __shfl_up_sync(0xffffffffu, dm.w, 1);
    float dr = __shfl_down_sync(0xffffffffu, dm.x, 1);
    if (lane == 0)  dl = hl;
    if (lane == 31) dr = hl;
    float4 hm;
    hm.x = fmax3(dl,   dm.x, dm.y);
    hm.y = fmax3(dm.x, dm.y, dm.z);
    hm.z = fmax3(dm.y, dm.z, dm.w);
    hm.w = fmax3(dm.z, dm.w, dr);
    return hm;
}

__global__ __launch_bounds__(256) void nms3d_kernel(const float* __restrict__ x,
                                                    float* __restrict__ out) {
    const int W = 1536, H = 1536;
    const long long plane = (long long)W * H;

    const int lane = threadIdx.x & 31;
    const int warp = threadIdx.x >> 5;
    const int tile_x = blockIdx.x;               // 0..11  (128-wide strips)
    const int strip  = blockIdx.y * 8 + warp;    // 0..95  (16-row strips)
    const int b      = blockIdx.z;

    const int w0 = tile_x * 128;
    const int y0 = strip * RS;
    const int col = w0 + lane * 4;

    // warp-edge halo pixel: lane 0 fetches w0-1, lane 31 fetches w0+128
    const int  hcol   = (lane == 0) ? (w0 - 1) : (w0 + 128);
    const bool hvalid = (lane == 0) ? (w0 > 0)
                                    : ((lane == 31) && (w0 + 128 < W));

    const float* xb = x   + (long long)b * 3 * plane;
    float*       ob = out + (long long)b * 3 * plane;

    float4 xdump[3];
    float4 xc[3], xn[3];
    float4 hm_m1 = row_hmax(xb, plane, W, H, y0 - 1, col, hcol, hvalid, lane, xdump);
    float4 hm_0  = row_hmax(xb, plane, W, H, y0,     col, hcol, hvalid, lane, xc);

#pragma unroll 4
    for (int j = 0; j < RS; j++) {
        float4 hm_p1 = row_hmax(xb, plane, W, H, y0 + j + 1, col, hcol, hvalid, lane, xn);

        float4 mp;
        mp.x = fmax3(hm_m1.x, hm_0.x, hm_p1.x);
        mp.y = fmax3(hm_m1.y, hm_0.y, hm_p1.y);
        mp.z = fmax3(hm_m1.z, hm_0.z, hm_p1.z);
        mp.w = fmax3(hm_m1.w, hm_0.w, hm_p1.w);

        float* po = ob + (long long)(y0 + j) * W + col;
#pragma unroll
        for (int d = 0; d < 3; d++) {
            float4 v = xc[d];
            float4 o;
            o.x = (v.x - mp.x + EPSV > 0.f) ? v.x : 0.f;
            o.y = (v.y - mp.y + EPSV > 0.f) ? v.y : 0.f;
            o.z = (v.z - mp.z + EPSV > 0.f) ? v.z : 0.f;
            o.w = (v.w - mp.w + EPSV > 0.f) ? v.w : 0.f;
            *(float4*)(po + d * plane) = o;
        }

        hm_m1 = hm_0; hm_0 = hm_p1;
        xc[0] = xn[0]; xc[1] = xn[1]; xc[2] = xn[2];
    }
}

extern "C" void kernel_launch(void* const* d_in, const int* in_sizes, int n_in,
                              void* d_out, int out_size) {
    const float* x = (const float*)d_in[0];
    float* out = (float*)d_out;
    dim3 grid(1536 / 128, (1536 / RS) / 8, 8);   // (12, 12, 8)
    nms3d_kernel<<<grid, 256>>>(x, out);
}